// round 17
// baseline (speedup 1.0000x reference)
#include <cuda_runtime.h>
#include <cuda_fp16.h>
#include <cstdint>
#include <cstring>

#define TT 2048
#define DIMX 1024
#define HIDX 4096
#define NEXP 8
#define NR 7
#define ALPHAF 2.0f
#define NST 3

// ---------------- device scratch ----------------
__device__ int g_count[NEXP];
__device__ int g_offset[NR];
__device__ int g_list[NR * TT];
__device__ float g_wtok[TT];
__device__ __half g_hr[(size_t)TT * HIDX];
__device__ __half g_hs[(size_t)TT * HIDX];
__device__ __half g_wu16[(size_t)NEXP * DIMX * HIDX];
__device__ __half g_wg16[(size_t)NEXP * DIMX * HIDX];
__device__ __half g_wd16[(size_t)NEXP * HIDX * DIMX];
__device__ __half g_x16[(size_t)TT * DIMX];

// ---------------- helpers ----------------
__device__ __forceinline__ uint32_t smem_u32(const void* p) {
    uint32_t a;
    asm("{ .reg .u64 t; cvta.to.shared.u64 t, %1; cvt.u32.u64 %0, t; }" : "=r"(a) : "l"(p));
    return a;
}
__device__ __forceinline__ void ldsm_x4(uint32_t* r, uint32_t addr) {
    asm volatile("ldmatrix.sync.aligned.m8n8.x4.shared.b16 {%0,%1,%2,%3}, [%4];"
                 : "=r"(r[0]), "=r"(r[1]), "=r"(r[2]), "=r"(r[3]) : "r"(addr));
}
__device__ __forceinline__ void ldsm_x2t(uint32_t* r, uint32_t addr) {
    asm volatile("ldmatrix.sync.aligned.m8n8.x2.trans.shared.b16 {%0,%1}, [%2];"
                 : "=r"(r[0]), "=r"(r[1]) : "r"(addr));
}
__device__ __forceinline__ void mma_f16(float* d, const uint32_t* a, const uint32_t* b) {
    asm volatile(
        "mma.sync.aligned.m16n8k16.row.col.f32.f16.f16.f32 "
        "{%0,%1,%2,%3}, {%4,%5,%6,%7}, {%8,%9}, {%0,%1,%2,%3};"
        : "+f"(d[0]), "+f"(d[1]), "+f"(d[2]), "+f"(d[3])
        : "r"(a[0]), "r"(a[1]), "r"(a[2]), "r"(a[3]), "r"(b[0]), "r"(b[1]));
}
__device__ __forceinline__ uint32_t h2_bits(__half2 h) {
    uint32_t u;
    memcpy(&u, &h, 4);
    return u;
}
__device__ __forceinline__ void cp16(uint32_t dst, const void* src) {
    asm volatile("cp.async.cg.shared.global [%0], [%1], 16;" :: "r"(dst), "l"(src));
}
#define CP_COMMIT() asm volatile("cp.async.commit_group;" ::: "memory")
#define CP_WAIT1()  asm volatile("cp.async.wait_group 1;" ::: "memory")

// ---------------- fp32 -> fp16 convert ----------------
__global__ void cvt_kernel(const float4* __restrict__ src, int which, size_t dst_off4, size_t n4) {
    __half* dbase = (which == 0) ? g_wu16 : (which == 1) ? g_wg16 : (which == 2) ? g_wd16 : g_x16;
    uint2* dst = reinterpret_cast<uint2*>(dbase) + dst_off4;
    size_t i = (size_t)blockIdx.x * blockDim.x + threadIdx.x;
    const size_t stride = (size_t)gridDim.x * blockDim.x;
    for (; i < n4; i += stride) {
        float4 v = src[i];
        uint2 o;
        o.x = h2_bits(__floats2half2_rn(v.x, v.y));
        o.y = h2_bits(__floats2half2_rn(v.z, v.w));
        dst[i] = o;
    }
}

// ---------------- small kernels ----------------
__global__ void init_kernel() {
    if (threadIdx.x < NEXP) g_count[threadIdx.x] = 0;
}

__global__ void router_kernel(const float* __restrict__ x, const float* __restrict__ wr) {
    __shared__ float sw[DIMX * NEXP];
    for (int i = threadIdx.x; i < DIMX * NEXP; i += blockDim.x) sw[i] = wr[i];
    __syncthreads();
    const int warp = threadIdx.x >> 5;
    const int lane = threadIdx.x & 31;
    const int tok = blockIdx.x * 8 + warp;
    if (tok >= TT) return;
    const float* xr = x + (size_t)tok * DIMX;
    float acc[NEXP];
#pragma unroll
    for (int e = 0; e < NEXP; ++e) acc[e] = 0.f;
    for (int k = lane; k < DIMX; k += 32) {
        float xv = xr[k];
#pragma unroll
        for (int e = 0; e < NEXP; ++e) acc[e] += xv * sw[k * NEXP + e];
    }
#pragma unroll
    for (int e = 0; e < NEXP; ++e)
#pragma unroll
        for (int o = 16; o; o >>= 1) acc[e] += __shfl_xor_sync(~0u, acc[e], o);
    if (lane == 0) {
        float m = acc[0];
        int idx = 0;
#pragma unroll
        for (int e = 1; e < NEXP; ++e)
            if (acc[e] > m) { m = acc[e]; idx = e; }
        float s = 0.f;
#pragma unroll
        for (int e = 0; e < NEXP; ++e) s += expf(acc[e] - m);
        g_wtok[tok] = ALPHAF / s;
        if (idx < NR) {
            int slot = atomicAdd(&g_count[idx], 1);
            g_list[idx * TT + slot] = tok;
        }
    }
}

__global__ void offsets_kernel() {
    if (threadIdx.x == 0) {
        int off = 0;
        for (int e = 0; e < NR; ++e) { g_offset[e] = off; off += g_count[e]; }
    }
}

// ---------------- upgate: BK=32, NST=3, one barrier/iter, fused SwiGLU ----------------
// A stage: 128 rows x 40 halves (32 + 8 pad). Bu/Bg stage: 32 rows x 72 halves.
#define UPG_AROW 40
#define UPG_BROW 72
#define UPG_A_STG (128 * UPG_AROW * 2)
#define UPG_B_STG (32 * UPG_BROW * 2)
#define UPG_SMEM (NST * (UPG_A_STG + 2 * UPG_B_STG))

__global__ __launch_bounds__(256, 2) void upgate_kernel() {
    const int g = blockIdx.z;
    int n_rows, base;
    __half* H;
    const int* lst;
    if (g < NR) {
        n_rows = g_count[g];
        H = g_hr; base = g_offset[g]; lst = g_list + g * TT;
    } else {
        n_rows = TT; H = g_hs; base = 0; lst = nullptr;
    }
    const int m0 = blockIdx.y * 128;
    if (m0 >= n_rows) return;
    const int n0 = blockIdx.x * 64;
    const __half* Wu = g_wu16 + (size_t)g * DIMX * HIDX;
    const __half* Wg = g_wg16 + (size_t)g * DIMX * HIDX;

    extern __shared__ __half smem[];
    const uint32_t As_u = smem_u32(smem);
    const uint32_t Bu_u = As_u + NST * UPG_A_STG;
    const uint32_t Bg_u = Bu_u + NST * UPG_B_STG;

    const int t = threadIdx.x;
    const int warp = t >> 5;
    const int lane = t & 31;
    const int wm = warp >> 2;   // 0..1
    const int wn = warp & 3;    // 0..3
    const int gid = lane >> 2;
    const int qp = lane & 3;

    // A producer: 2 chunks/thread. chunk c: row c>>2 (0..127), sub (c&3)*8 halves.
    const int ar0 = t >> 2, asub = (t & 3) * 8;   // rows 0..63
    const int ar1 = ar0 + 64;                      // rows 64..127
    int mm0 = m0 + ar0; if (mm0 >= n_rows) mm0 = n_rows - 1;
    int mm1 = m0 + ar1; if (mm1 >= n_rows) mm1 = n_rows - 1;
    const __half* aptr0 = g_x16 + (size_t)((g < NR) ? lst[mm0] : mm0) * DIMX + asub;
    const __half* aptr1 = g_x16 + (size_t)((g < NR) ? lst[mm1] : mm1) * DIMX + asub;
    const uint32_t adst0 = As_u + (uint32_t)((ar0 * UPG_AROW + asub) * 2);
    const uint32_t adst1 = As_u + (uint32_t)((ar1 * UPG_AROW + asub) * 2);
    // B producer: 1 Bu + 1 Bg chunk/thread: row t>>3 (0..31), col (t&7)*8
    const int bk = t >> 3, bn = (t & 7) * 8;
    const __half* buptr = Wu + (size_t)bk * HIDX + n0 + bn;
    const __half* bgptr = Wg + (size_t)bk * HIDX + n0 + bn;
    const uint32_t budst = Bu_u + (uint32_t)((bk * UPG_BROW + bn) * 2);
    const uint32_t bgdst = Bg_u + (uint32_t)((bk * UPG_BROW + bn) * 2);

    const int KT = DIMX / 32;  // 32

    // consumer bases
    const int lr = (lane & 7) + ((lane >> 3) & 1) * 8;
    const int lk = (lane >> 4) * 8;
    const uint32_t asb = As_u + (uint32_t)(((wm * 64 + lr) * UPG_AROW + lk) * 2);
    const int bl = lane & 15;
    const uint32_t bub = Bu_u + (uint32_t)((bl * UPG_BROW + wn * 16) * 2);
    const uint32_t bgb = Bg_u + (uint32_t)((bl * UPG_BROW + wn * 16) * 2);

    float accU[4][2][4], accG[4][2][4];
#pragma unroll
    for (int i = 0; i < 4; ++i)
#pragma unroll
        for (int j = 0; j < 2; ++j)
#pragma unroll
            for (int k = 0; k < 4; ++k) { accU[i][j][k] = 0.f; accG[i][j][k] = 0.f; }

    // prologue: stages 0,1
#pragma unroll
    for (int p = 0; p < NST - 1; ++p) {
        const int ko = p * 32;
        cp16(adst0 + p * UPG_A_STG, aptr0 + ko);
        cp16(adst1 + p * UPG_A_STG, aptr1 + ko);
        cp16(budst + p * UPG_B_STG, buptr + (size_t)ko * HIDX);
        cp16(bgdst + p * UPG_B_STG, bgptr + (size_t)ko * HIDX);
        CP_COMMIT();
    }

    int s = 0, sn = NST - 1;
    for (int kt = 0; kt < KT; ++kt) {
        CP_WAIT1();
        __syncthreads();
        {
            const int kn = kt + NST - 1;
            if (kn < KT) {
                const int ko = kn * 32;
                cp16(adst0 + sn * UPG_A_STG, aptr0 + ko);
                cp16(adst1 + sn * UPG_A_STG, aptr1 + ko);
                cp16(budst + sn * UPG_B_STG, buptr + (size_t)ko * HIDX);
                cp16(bgdst + sn * UPG_B_STG, bgptr + (size_t)ko * HIDX);
            }
            CP_COMMIT();
        }
#pragma unroll
        for (int ks = 0; ks < 2; ++ks) {
            uint32_t a[4][4], bu[2][2], bg[2][2];
            const uint32_t sa = asb + (uint32_t)(s * UPG_A_STG + ks * 32);
            const uint32_t su = bub + (uint32_t)(s * UPG_B_STG + ks * 16 * UPG_BROW * 2);
            const uint32_t sg = bgb + (uint32_t)(s * UPG_B_STG + ks * 16 * UPG_BROW * 2);
#pragma unroll
            for (int mf = 0; mf < 4; ++mf) ldsm_x4(a[mf], sa + (uint32_t)(mf * 16 * UPG_AROW * 2));
#pragma unroll
            for (int nf = 0; nf < 2; ++nf) {
                ldsm_x2t(bu[nf], su + (uint32_t)(nf * 8 * 2));
                ldsm_x2t(bg[nf], sg + (uint32_t)(nf * 8 * 2));
            }
#pragma unroll
            for (int mf = 0; mf < 4; ++mf)
#pragma unroll
                for (int nf = 0; nf < 2; ++nf) {
                    mma_f16(accU[mf][nf], a[mf], bu[nf]);
                    mma_f16(accG[mf][nf], a[mf], bg[nf]);
                }
        }
        s = (s + 1 == NST) ? 0 : s + 1;
        sn = (sn + 1 == NST) ? 0 : sn + 1;
    }

    // epilogue: h = up * silu(gate) -> fp16
#pragma unroll
    for (int mf = 0; mf < 4; ++mf)
#pragma unroll
        for (int nf = 0; nf < 2; ++nf) {
            const int col = n0 + wn * 16 + nf * 8 + qp * 2;
#pragma unroll
            for (int half = 0; half < 2; ++half) {
                const int m = m0 + wm * 64 + mf * 16 + gid + half * 8;
                if (m < n_rows) {
                    float u0 = accU[mf][nf][half * 2 + 0];
                    float u1 = accU[mf][nf][half * 2 + 1];
                    float gv0 = accG[mf][nf][half * 2 + 0];
                    float gv1 = accG[mf][nf][half * 2 + 1];
                    float h0 = u0 * (gv0 / (1.f + expf(-gv0)));
                    float h1 = u1 * (gv1 / (1.f + expf(-gv1)));
                    __half2 hv = __floats2half2_rn(h0, h1);
                    *(__half2*)(H + (size_t)(base + m) * HIDX + col) = hv;
                }
            }
        }
}

// ---------------- down: BK=32, NST=3, one barrier/iter ----------------
#define DWN_AROW 40
#define DWN_BROW 136
#define DWN_A_STG (128 * DWN_AROW * 2)
#define DWN_B_STG (32 * DWN_BROW * 2)
#define DWN_SMEM (NST * (DWN_A_STG + DWN_B_STG))

__global__ __launch_bounds__(256, 2) void down_kernel(float* __restrict__ out, int shared_mode) {
    int n_rows, base;
    const __half* Wd;
    const __half* Hsrc;
    const int* lst;
    if (shared_mode) {
        n_rows = TT; Wd = g_wd16 + (size_t)NR * HIDX * DIMX; Hsrc = g_hs; base = 0; lst = nullptr;
    } else {
        const int g = blockIdx.z;
        n_rows = g_count[g];
        Wd = g_wd16 + (size_t)g * HIDX * DIMX;
        Hsrc = g_hr; base = g_offset[g]; lst = g_list + g * TT;
    }
    const int m0 = blockIdx.y * 128;
    if (m0 >= n_rows) return;
    const int n0 = blockIdx.x * 128;

    extern __shared__ __half smem[];
    const uint32_t As_u = smem_u32(smem);
    const uint32_t Bs_u = As_u + NST * DWN_A_STG;

    const int t = threadIdx.x;
    const int warp = t >> 5;
    const int lane = t & 31;
    const int wm = warp >> 2;
    const int wn = warp & 3;
    const int gid = lane >> 2;
    const int qp = lane & 3;

    const int ar0 = t >> 2, asub = (t & 3) * 8;
    const int ar1 = ar0 + 64;
    int mm0 = m0 + ar0; if (mm0 >= n_rows) mm0 = n_rows - 1;
    int mm1 = m0 + ar1; if (mm1 >= n_rows) mm1 = n_rows - 1;
    const __half* aptr0 = Hsrc + (size_t)(base + mm0) * HIDX + asub;
    const __half* aptr1 = Hsrc + (size_t)(base + mm1) * HIDX + asub;
    const uint32_t adst0 = As_u + (uint32_t)((ar0 * DWN_AROW + asub) * 2);
    const uint32_t adst1 = As_u + (uint32_t)((ar1 * DWN_AROW + asub) * 2);
    // B: 2 chunks/thread: rows t>>4 and 16+(t>>4), col (t&15)*8
    const int br0 = t >> 4, br1 = 16 + (t >> 4), bcol = (t & 15) * 8;
    const __half* bptr0 = Wd + (size_t)br0 * DIMX + n0 + bcol;
    const __half* bptr1 = Wd + (size_t)br1 * DIMX + n0 + bcol;
    const uint32_t bdst0 = Bs_u + (uint32_t)((br0 * DWN_BROW + bcol) * 2);
    const uint32_t bdst1 = Bs_u + (uint32_t)((br1 * DWN_BROW + bcol) * 2);

    const int KT = HIDX / 32;  // 128

    const int lr = (lane & 7) + ((lane >> 3) & 1) * 8;
    const int lk = (lane >> 4) * 8;
    const uint32_t asb = As_u + (uint32_t)(((wm * 64 + lr) * DWN_AROW + lk) * 2);
    const int bl = lane & 15;
    const uint32_t bsb = Bs_u + (uint32_t)((bl * DWN_BROW + wn * 32) * 2);

    float acc[4][4][4];
#pragma unroll
    for (int i = 0; i < 4; ++i)
#pragma unroll
        for (int j = 0; j < 4; ++j)
#pragma unroll
            for (int k = 0; k < 4; ++k) acc[i][j][k] = 0.f;

#pragma unroll
    for (int p = 0; p < NST - 1; ++p) {
        const int ko = p * 32;
        cp16(adst0 + p * DWN_A_STG, aptr0 + ko);
        cp16(adst1 + p * DWN_A_STG, aptr1 + ko);
        cp16(bdst0 + p * DWN_B_STG, bptr0 + (size_t)ko * DIMX);
        cp16(bdst1 + p * DWN_B_STG, bptr1 + (size_t)ko * DIMX);
        CP_COMMIT();
    }

    int s = 0, sn = NST - 1;
    for (int kt = 0; kt < KT; ++kt) {
        CP_WAIT1();
        __syncthreads();
        {
            const int kn = kt + NST - 1;
            if (kn < KT) {
                const int ko = kn * 32;
                cp16(adst0 + sn * DWN_A_STG, aptr0 + ko);
                cp16(adst1 + sn * DWN_A_STG, aptr1 + ko);
                cp16(bdst0 + sn * DWN_B_STG, bptr0 + (size_t)ko * DIMX);
                cp16(bdst1 + sn * DWN_B_STG, bptr1 + (size_t)ko * DIMX);
            }
            CP_COMMIT();
        }
#pragma unroll
        for (int ks = 0; ks < 2; ++ks) {
            uint32_t a[4][4], b[4][2];
            const uint32_t sa = asb + (uint32_t)(s * DWN_A_STG + ks * 32);
            const uint32_t sbv = bsb + (uint32_t)(s * DWN_B_STG + ks * 16 * DWN_BROW * 2);
#pragma unroll
            for (int mf = 0; mf < 4; ++mf) ldsm_x4(a[mf], sa + (uint32_t)(mf * 16 * DWN_AROW * 2));
#pragma unroll
            for (int nf = 0; nf < 4; ++nf) ldsm_x2t(b[nf], sbv + (uint32_t)(nf * 8 * 2));
#pragma unroll
            for (int mf = 0; mf < 4; ++mf)
#pragma unroll
                for (int nf = 0; nf < 4; ++nf) mma_f16(acc[mf][nf], a[mf], b[nf]);
        }
        s = (s + 1 == NST) ? 0 : s + 1;
        sn = (sn + 1 == NST) ? 0 : sn + 1;
    }

#pragma unroll
    for (int mf = 0; mf < 4; ++mf)
#pragma unroll
        for (int nf = 0; nf < 4; ++nf) {
            const int col = n0 + wn * 32 + nf * 8 + qp * 2;
#pragma unroll
            for (int half = 0; half < 2; ++half) {
                const int m = m0 + wm * 64 + mf * 16 + gid + half * 8;
                if (m < n_rows) {
                    float v0 = acc[mf][nf][half * 2 + 0];
                    float v1 = acc[mf][nf][half * 2 + 1];
                    if (shared_mode) {
                        *(float2*)(out + (size_t)m * DIMX + col) = make_float2(v0, v1);
                    } else {
                        const int tok = lst[m];
                        const float w = g_wtok[tok];
                        float2* p = (float2*)(out + (size_t)tok * DIMX + col);
                        float2 o = *p;
                        o.x += w * v0;
                        o.y += w * v1;
                        *p = o;
                    }
                }
            }
        }
}

// ---------------- launch ----------------
extern "C" void kernel_launch(void* const* d_in, const int* in_sizes, int n_in,
                              void* d_out, int out_size) {
    (void)in_sizes; (void)n_in; (void)out_size;
    const float* x = (const float*)d_in[0];
    const float* w_router = (const float*)d_in[1];
    const float* w_up = (const float*)d_in[2];
    const float* w_gate = (const float*)d_in[3];
    const float* w_down = (const float*)d_in[4];
    const float* ws_up = (const float*)d_in[5];
    const float* ws_gate = (const float*)d_in[6];
    const float* ws_down = (const float*)d_in[7];
    float* out = (float*)d_out;

    const size_t WE4 = (size_t)DIMX * HIDX / 4;
    const size_t W7_4 = (size_t)NR * DIMX * HIDX / 4;

    cudaFuncSetAttribute(upgate_kernel, cudaFuncAttributeMaxDynamicSharedMemorySize, UPG_SMEM);
    cudaFuncSetAttribute(down_kernel, cudaFuncAttributeMaxDynamicSharedMemorySize, DWN_SMEM);

    init_kernel<<<1, 32>>>();
    router_kernel<<<TT / 8, 256>>>(x, w_router);
    offsets_kernel<<<1, 32>>>();
    cvt_kernel<<<4096, 256>>>((const float4*)w_up,    0, 0,        W7_4);
    cvt_kernel<<<1024, 256>>>((const float4*)ws_up,   0, NR * WE4, WE4);
    cvt_kernel<<<4096, 256>>>((const float4*)w_gate,  1, 0,        W7_4);
    cvt_kernel<<<1024, 256>>>((const float4*)ws_gate, 1, NR * WE4, WE4);
    cvt_kernel<<<4096, 256>>>((const float4*)w_down,  2, 0,        W7_4);
    cvt_kernel<<<1024, 256>>>((const float4*)ws_down, 2, NR * WE4, WE4);
    cvt_kernel<<<512, 256>>>((const float4*)x,        3, 0, (size_t)TT * DIMX / 4);

    upgate_kernel<<<dim3(HIDX / 64, TT / 128, NEXP), 256, UPG_SMEM>>>();
    down_kernel<<<dim3(DIMX / 128, TT / 128, 1), 256, DWN_SMEM>>>(out, 1);
    down_kernel<<<dim3(DIMX / 128, TT / 128, NR), 256, DWN_SMEM>>>(out, 0);
}